// round 3
// baseline (speedup 1.0000x reference)
#include <cuda_runtime.h>
#include <math.h>

#define NTOK   8192      // B*S
#define DMODEL 1024
#define NHEAD  8
#define HDK    128
#define DFF    4096
#define SEQ    2048
#define BATCH  4

// ---------------- scratch (no allocations allowed) ----------------
__device__ float gQ[NTOK * DMODEL];     // [B,H,S,dk]
__device__ float gK[NTOK * DMODEL];
__device__ float gV[NTOK * DMODEL];
__device__ float gAtt[NTOK * DMODEL];   // [B,S,D]
__device__ float gX1[NTOK * DMODEL];
__device__ float gH1[(size_t)NTOK * DFF];
__device__ float gH2[NTOK * DMODEL];

// ---------------- SGEMM: C = A[MxK] @ B[KxN] + bias ----------------
// EPI: 0 = bias, 1 = bias+relu, 2 = bias + scatter to [B,H,S,dk]
template <int EPI>
__global__ __launch_bounds__(256) void sgemm_kernel(
    const float* __restrict__ A, const float* __restrict__ B,
    const float* __restrict__ bias, float* __restrict__ C,
    int M, int N, int K)
{
    __shared__ float As[8][128];
    __shared__ float Bs[8][128];

    const int tid = threadIdx.x;
    const int bm = blockIdx.y * 128;
    const int bn = blockIdx.x * 128;

    const int arow = tid >> 1, acol = (tid & 1) * 4;
    const int brow = tid >> 5, bcol = (tid & 31) * 4;
    const float* Ap = A + (size_t)(bm + arow) * K + acol;
    const float* Bp = B + (size_t)brow * N + bn + bcol;

    const int tx = tid & 15, ty = tid >> 4;

    float acc[8][8];
#pragma unroll
    for (int i = 0; i < 8; i++)
#pragma unroll
        for (int j = 0; j < 8; j++) acc[i][j] = 0.f;

    for (int k0 = 0; k0 < K; k0 += 8) {
        float4 av = *(const float4*)Ap;
        float4 bv = *(const float4*)Bp;
        Ap += 8;
        Bp += (size_t)8 * N;
        As[acol + 0][arow] = av.x;
        As[acol + 1][arow] = av.y;
        As[acol + 2][arow] = av.z;
        As[acol + 3][arow] = av.w;
        *(float4*)&Bs[brow][bcol] = bv;
        __syncthreads();
#pragma unroll
        for (int k = 0; k < 8; k++) {
            float ra[8], rb[8];
            *(float4*)&ra[0] = *(const float4*)&As[k][ty * 8];
            *(float4*)&ra[4] = *(const float4*)&As[k][ty * 8 + 4];
            *(float4*)&rb[0] = *(const float4*)&Bs[k][tx * 8];
            *(float4*)&rb[4] = *(const float4*)&Bs[k][tx * 8 + 4];
#pragma unroll
            for (int i = 0; i < 8; i++)
#pragma unroll
                for (int j = 0; j < 8; j++)
                    acc[i][j] = fmaf(ra[i], rb[j], acc[i][j]);
        }
        __syncthreads();
    }

#pragma unroll
    for (int i = 0; i < 8; i++) {
        const int row = bm + ty * 8 + i;
#pragma unroll
        for (int jj = 0; jj < 2; jj++) {
            const int col0 = bn + tx * 8 + jj * 4;
            float4 v;
            v.x = acc[i][jj * 4 + 0] + bias[col0 + 0];
            v.y = acc[i][jj * 4 + 1] + bias[col0 + 1];
            v.z = acc[i][jj * 4 + 2] + bias[col0 + 2];
            v.w = acc[i][jj * 4 + 3] + bias[col0 + 3];
            if (EPI == 1) {
                v.x = fmaxf(v.x, 0.f); v.y = fmaxf(v.y, 0.f);
                v.z = fmaxf(v.z, 0.f); v.w = fmaxf(v.w, 0.f);
            }
            if (EPI == 2) {
                const int b = row >> 11, s = row & 2047;
                const int h = col0 >> 7, d = col0 & 127;
                const size_t dst = (((size_t)(b * NHEAD + h) * SEQ + s) * HDK) + d;
                *(float4*)&C[dst] = v;
            } else {
                *(float4*)&C[(size_t)row * N + col0] = v;
            }
        }
    }
}

// ---------------- Flash attention ----------------
// Q,K,V: [B*H, S, dk] fp32.  Out: [B,S,D].
// Grid: (S/64, B*H), 256 threads, dynamic smem.
__global__ __launch_bounds__(256) void attn_kernel(
    const float* __restrict__ Q, const float* __restrict__ K,
    const float* __restrict__ V, float* __restrict__ Out)
{
    extern __shared__ float sm[];
    float* sQ  = sm;                       // 64*129
    float* sK  = sm + 64 * 129;            // 64*129
    float* sV  = sm + 2 * 64 * 129;        // 64*129
    float* sS  = sm + 3 * 64 * 129;        // 64*65
    float* sMr = sS + 64 * 65;             // 64
    float* sLr = sMr + 64;                 // 64
    float* sAl = sLr + 64;                 // 64

    const int tid = threadIdx.x;
    const int bh = blockIdx.y;
    const int q0 = blockIdx.x * 64;

    const float* Qh = Q + (size_t)bh * SEQ * HDK;
    const float* Kh = K + (size_t)bh * SEQ * HDK;
    const float* Vh = V + (size_t)bh * SEQ * HDK;

    // load Q tile (64x128) with pad-129 rows
    for (int idx = tid * 4; idx < 64 * 128; idx += 256 * 4) {
        const int r = idx >> 7, c = idx & 127;
        float4 v = *(const float4*)&Qh[(size_t)(q0 + r) * HDK + c];
        sQ[r * 129 + c + 0] = v.x;
        sQ[r * 129 + c + 1] = v.y;
        sQ[r * 129 + c + 2] = v.z;
        sQ[r * 129 + c + 3] = v.w;
    }
    if (tid < 64) { sMr[tid] = -INFINITY; sLr[tid] = 0.f; }

    const int i1 = (tid >> 4) * 4;   // row base (phases 1 & 3)
    const int j1 = (tid & 15) * 4;   // col base phase 1
    const int d3 = (tid & 15) * 8;   // col base phase 3

    float o[4][8];
#pragma unroll
    for (int i = 0; i < 4; i++)
#pragma unroll
        for (int d = 0; d < 8; d++) o[i][d] = 0.f;

    const float scale = 0.08838834764831845f;  // 1/sqrt(128)

    for (int kv0 = 0; kv0 < SEQ; kv0 += 64) {
        __syncthreads();  // sK/sV/sS free to overwrite; also covers sQ/sMr init
        for (int idx = tid * 4; idx < 64 * 128; idx += 256 * 4) {
            const int r = idx >> 7, c = idx & 127;
            float4 kv = *(const float4*)&Kh[(size_t)(kv0 + r) * HDK + c];
            sK[r * 129 + c + 0] = kv.x;
            sK[r * 129 + c + 1] = kv.y;
            sK[r * 129 + c + 2] = kv.z;
            sK[r * 129 + c + 3] = kv.w;
            float4 vv = *(const float4*)&Vh[(size_t)(kv0 + r) * HDK + c];
            sV[r * 129 + c + 0] = vv.x;
            sV[r * 129 + c + 1] = vv.y;
            sV[r * 129 + c + 2] = vv.z;
            sV[r * 129 + c + 3] = vv.w;
        }
        __syncthreads();

        // Phase 1: S(64x64) = Q @ K^T * scale
        float sa[4][4];
#pragma unroll
        for (int i = 0; i < 4; i++)
#pragma unroll
            for (int j = 0; j < 4; j++) sa[i][j] = 0.f;
#pragma unroll 8
        for (int k = 0; k < 128; k++) {
            float ra[4], rb[4];
#pragma unroll
            for (int ii = 0; ii < 4; ii++) ra[ii] = sQ[(i1 + ii) * 129 + k];
#pragma unroll
            for (int jj = 0; jj < 4; jj++) rb[jj] = sK[(j1 + jj) * 129 + k];
#pragma unroll
            for (int ii = 0; ii < 4; ii++)
#pragma unroll
                for (int jj = 0; jj < 4; jj++)
                    sa[ii][jj] = fmaf(ra[ii], rb[jj], sa[ii][jj]);
        }
#pragma unroll
        for (int ii = 0; ii < 4; ii++)
#pragma unroll
            for (int jj = 0; jj < 4; jj++)
                sS[(i1 + ii) * 65 + j1 + jj] = sa[ii][jj] * scale;
        __syncthreads();

        // Phase 2: online softmax (4 threads per row)
        {
            const int row = tid >> 2, l4 = tid & 3;
            float* Sr = sS + row * 65 + l4 * 16;
            float tmax = -INFINITY;
#pragma unroll
            for (int j = 0; j < 16; j++) tmax = fmaxf(tmax, Sr[j]);
            tmax = fmaxf(tmax, __shfl_xor_sync(0xffffffffu, tmax, 1));
            tmax = fmaxf(tmax, __shfl_xor_sync(0xffffffffu, tmax, 2));
            const float mold = sMr[row];
            const float mnew = fmaxf(mold, tmax);
            float psum = 0.f;
#pragma unroll
            for (int j = 0; j < 16; j++) {
                const float p = __expf(Sr[j] - mnew);
                Sr[j] = p;
                psum += p;
            }
            psum += __shfl_xor_sync(0xffffffffu, psum, 1);
            psum += __shfl_xor_sync(0xffffffffu, psum, 2);
            if (l4 == 0) {
                const float alpha = __expf(mold - mnew);
                sAl[row] = alpha;
                sLr[row] = alpha * sLr[row] + psum;
                sMr[row] = mnew;
            }
        }
        __syncthreads();

        // Phase 3: O = alpha*O + P @ V
        float al[4];
#pragma unroll
        for (int ii = 0; ii < 4; ii++) al[ii] = sAl[i1 + ii];
#pragma unroll
        for (int ii = 0; ii < 4; ii++)
#pragma unroll
            for (int dd = 0; dd < 8; dd++) o[ii][dd] *= al[ii];
#pragma unroll 4
        for (int kk = 0; kk < 64; kk++) {
            float rp[4], rv[8];
#pragma unroll
            for (int ii = 0; ii < 4; ii++) rp[ii] = sS[(i1 + ii) * 65 + kk];
#pragma unroll
            for (int dd = 0; dd < 8; dd++) rv[dd] = sV[kk * 129 + d3 + dd];
#pragma unroll
            for (int ii = 0; ii < 4; ii++)
#pragma unroll
                for (int dd = 0; dd < 8; dd++)
                    o[ii][dd] = fmaf(rp[ii], rv[dd], o[ii][dd]);
        }
    }

    // epilogue: divide by l, write [B,S,D]
    const int b = bh >> 3, h = bh & 7;
#pragma unroll
    for (int ii = 0; ii < 4; ii++) {
        const int qrow = q0 + i1 + ii;
        const float linv = 1.f / sLr[i1 + ii];
        float* dst = Out + (size_t)(b * SEQ + qrow) * DMODEL + h * HDK + d3;
        float4 v0, v1;
        v0.x = o[ii][0] * linv; v0.y = o[ii][1] * linv;
        v0.z = o[ii][2] * linv; v0.w = o[ii][3] * linv;
        v1.x = o[ii][4] * linv; v1.y = o[ii][5] * linv;
        v1.z = o[ii][6] * linv; v1.w = o[ii][7] * linv;
        *(float4*)dst = v0;
        *(float4*)(dst + 4) = v1;
    }
}

// ---------------- residual add + LayerNorm ----------------
// out[row] = LN(a[row] + b[row]) * g + beta   (row = 1024 elems)
__global__ __launch_bounds__(256) void add_ln_kernel(
    const float* __restrict__ A, const float* __restrict__ B,
    const float* __restrict__ g, const float* __restrict__ beta,
    float* __restrict__ out)
{
    __shared__ float red[8];
    const int row = blockIdx.x, tid = threadIdx.x;
    const float* pa = A + (size_t)row * DMODEL;
    const float* pb = B + (size_t)row * DMODEL;

    float v[4];
    float s = 0.f;
#pragma unroll
    for (int i = 0; i < 4; i++) {
        const int c = tid + i * 256;
        v[i] = pa[c] + pb[c];
        s += v[i];
    }
#pragma unroll
    for (int off = 16; off; off >>= 1) s += __shfl_xor_sync(0xffffffffu, s, off);
    if ((tid & 31) == 0) red[tid >> 5] = s;
    __syncthreads();
    float tot = 0.f;
#pragma unroll
    for (int w = 0; w < 8; w++) tot += red[w];
    const float mu = tot * (1.f / 1024.f);

    float vs = 0.f;
#pragma unroll
    for (int i = 0; i < 4; i++) {
        const float d = v[i] - mu;
        vs += d * d;
    }
#pragma unroll
    for (int off = 16; off; off >>= 1) vs += __shfl_xor_sync(0xffffffffu, vs, off);
    __syncthreads();
    if ((tid & 31) == 0) red[tid >> 5] = vs;
    __syncthreads();
    float vtot = 0.f;
#pragma unroll
    for (int w = 0; w < 8; w++) vtot += red[w];
    const float rs = rsqrtf(vtot * (1.f / 1024.f) + 1e-6f);

    float* po = out + (size_t)row * DMODEL;
#pragma unroll
    for (int i = 0; i < 4; i++) {
        const int c = tid + i * 256;
        po[c] = (v[i] - mu) * rs * g[c] + beta[c];
    }
}

// ---------------- launch ----------------
extern "C" void kernel_launch(void* const* d_in, const int* in_sizes, int n_in,
                              void* d_out, int out_size)
{
    const float* x     = (const float*)d_in[0];
    const float* Wq    = (const float*)d_in[1];
    const float* bq    = (const float*)d_in[2];
    const float* Wk    = (const float*)d_in[3];
    const float* bk    = (const float*)d_in[4];
    const float* Wv    = (const float*)d_in[5];
    const float* bv    = (const float*)d_in[6];
    const float* ln1_g = (const float*)d_in[7];
    const float* ln1_b = (const float*)d_in[8];
    const float* W1    = (const float*)d_in[9];
    const float* b1    = (const float*)d_in[10];
    const float* W2    = (const float*)d_in[11];
    const float* b2    = (const float*)d_in[12];
    const float* ln2_g = (const float*)d_in[13];
    const float* ln2_b = (const float*)d_in[14];
    float* out = (float*)d_out;

    float *Qp, *Kp, *Vp, *Attp, *X1p, *H1p, *H2p;
    cudaGetSymbolAddress((void**)&Qp, gQ);
    cudaGetSymbolAddress((void**)&Kp, gK);
    cudaGetSymbolAddress((void**)&Vp, gV);
    cudaGetSymbolAddress((void**)&Attp, gAtt);
    cudaGetSymbolAddress((void**)&X1p, gX1);
    cudaGetSymbolAddress((void**)&H1p, gH1);
    cudaGetSymbolAddress((void**)&H2p, gH2);

    const dim3 blk(256);

    // QKV projections, scattered into [B,H,S,dk]
    sgemm_kernel<2><<<dim3(8, 64), blk>>>(x, Wq, bq, Qp, NTOK, DMODEL, DMODEL);
    sgemm_kernel<2><<<dim3(8, 64), blk>>>(x, Wk, bk, Kp, NTOK, DMODEL, DMODEL);
    sgemm_kernel<2><<<dim3(8, 64), blk>>>(x, Wv, bv, Vp, NTOK, DMODEL, DMODEL);

    // flash attention
    const int smem = (3 * 64 * 129 + 64 * 65 + 3 * 64) * sizeof(float);  // 116480 B
    cudaFuncSetAttribute(attn_kernel, cudaFuncAttributeMaxDynamicSharedMemorySize, smem);
    attn_kernel<<<dim3(SEQ / 64, BATCH * NHEAD), blk, smem>>>(Qp, Kp, Vp, Attp);

    // x1 = LN(att + x)
    add_ln_kernel<<<NTOK, blk>>>(Attp, x, ln1_g, ln1_b, X1p);

    // FFN
    sgemm_kernel<1><<<dim3(32, 64), blk>>>(X1p, W1, b1, H1p, NTOK, DFF, DMODEL);
    sgemm_kernel<0><<<dim3(8, 64), blk>>>(H1p, W2, b2, H2p, NTOK, DMODEL, DFF);

    // out = LN(h2 + x1)
    add_ln_kernel<<<NTOK, blk>>>(H2p, X1p, ln2_g, ln2_b, out);
}

// round 8
// speedup vs baseline: 1.6810x; 1.6810x over previous
#include <cuda_runtime.h>
#include <math.h>
#include <stdint.h>

#define NTOK   8192      // B*S
#define DMODEL 1024
#define NHEAD  8
#define HDK    128
#define DFF    4096
#define SEQ    2048
#define BATCH  4

// ---------------- scratch (no allocations allowed) ----------------
__device__ float gQ[NTOK * DMODEL];     // [B,H,S,dk]
__device__ float gK[NTOK * DMODEL];
__device__ float gV[NTOK * DMODEL];
__device__ float gAtt[NTOK * DMODEL];   // [B,S,D]
__device__ float gX1[NTOK * DMODEL];
__device__ float gH1[(size_t)NTOK * DFF];
__device__ float gH2[NTOK * DMODEL];

// ============== helpers ==============
__device__ __forceinline__ uint32_t smem_u32(const void* p) {
    uint32_t a;
    asm("{ .reg .u64 t; cvta.to.shared.u64 t, %1; cvt.u32.u64 %0, t; }"
        : "=r"(a) : "l"(p));
    return a;
}
__device__ __forceinline__ uint32_t f2tf32(float x) {
    uint32_t u;
    asm("cvt.rna.tf32.f32 %0, %1;" : "=r"(u) : "f"(x));
    return u;
}
__device__ __forceinline__ void sts128(uint32_t addr, uint32_t a, uint32_t b,
                                       uint32_t c, uint32_t d) {
    asm volatile("st.shared.v4.b32 [%0], {%1,%2,%3,%4};"
                 :: "r"(addr), "r"(a), "r"(b), "r"(c), "r"(d) : "memory");
}
// m16n8k8 tf32 MMA (portable tensor-core path; no sm_103a-only features)
__device__ __forceinline__ void mma16n8k8(float* c, const uint32_t* a,
                                          const uint32_t* b) {
    asm volatile(
        "mma.sync.aligned.m16n8k8.row.col.f32.tf32.tf32.f32 "
        "{%0,%1,%2,%3}, {%4,%5,%6,%7}, {%8,%9}, {%0,%1,%2,%3};"
        : "+f"(c[0]), "+f"(c[1]), "+f"(c[2]), "+f"(c[3])
        : "r"(a[0]), "r"(a[1]), "r"(a[2]), "r"(a[3]), "r"(b[0]), "r"(b[1]));
}

// ============== tf32 tensor-core GEMM: C[M,N] = A[M,K] @ B[K,N] + bias ==============
// Tile 128x128, BK=32, 256 thr (8 warps, 4x2), warp tile 32x64.
// EPI: 0=bias, 1=bias+relu, 2=bias+head scatter to [B,H,S,dk]
#define BK 32
#define APAD 36    // words per A row  (128 rows)
#define BPAD 136   // words per B row  (32 rows)
#define SW_A (128 * APAD)            // 4608 words
#define SW_B (BK * BPAD)             // 4352 words
#define STG_WORDS (SW_A + SW_B)      // 8960 words per stage
#define GEMM_SMEM (2 * STG_WORDS * 4)

template <int EPI>
__global__ __launch_bounds__(256) void tc_gemm(
    const float* __restrict__ A, const float* __restrict__ B,
    const float* __restrict__ bias, float* __restrict__ C,
    int M, int N, int K)
{
    extern __shared__ uint32_t smw[];

    const int tid = threadIdx.x;
    const int wid = tid >> 5, lane = tid & 31;
    const int qrow = lane >> 2, qcol = lane & 3;
    const int wm0 = (wid & 3) * 32;
    const int wn0 = (wid >> 2) * 64;

    const int bm = blockIdx.y * 128;
    const int bn = blockIdx.x * 128;
    const int KC = K >> 5;

    // per-thread global load coords (4 float4 each for A and B)
    const int ar = tid >> 1;                 // base pattern via idx = t*256+tid
    (void)ar;

    float acc[2][8][4];
#pragma unroll
    for (int mt = 0; mt < 2; mt++)
#pragma unroll
        for (int nt = 0; nt < 8; nt++)
#pragma unroll
            for (int q = 0; q < 4; q++) acc[mt][nt][q] = 0.f;

    // ---- prologue: load chunk 0, store to stage 0 ----
    {
#pragma unroll
        for (int t = 0; t < 4; t++) {
            const int idx = t * 256 + tid;
            const int r = idx >> 3, c = (idx & 7) * 4;
            float4 v = *(const float4*)(A + (size_t)(bm + r) * K + c);
            sts128(smem_u32(&smw[r * APAD + c]),
                   f2tf32(v.x), f2tf32(v.y), f2tf32(v.z), f2tf32(v.w));
            const int k = idx >> 5, c2 = (idx & 31) * 4;
            float4 w = *(const float4*)(B + (size_t)k * N + bn + c2);
            sts128(smem_u32(&smw[SW_A + k * BPAD + c2]),
                   f2tf32(w.x), f2tf32(w.y), f2tf32(w.z), f2tf32(w.w));
        }
    }
    __syncthreads();

    for (int i = 0; i < KC; i++) {
        const int cur = i & 1;
        float4 aR[4], bR[4];
        if (i + 1 < KC) {
            const int k1 = (i + 1) << 5;
#pragma unroll
            for (int t = 0; t < 4; t++) {
                const int idx = t * 256 + tid;
                const int r = idx >> 3, c = (idx & 7) * 4;
                aR[t] = *(const float4*)(A + (size_t)(bm + r) * K + k1 + c);
                const int k = idx >> 5, c2 = (idx & 31) * 4;
                bR[t] = *(const float4*)(B + (size_t)(k1 + k) * N + bn + c2);
            }
        }

        // ---- compute from stage `cur` ----
        const uint32_t* pA = smw + cur * STG_WORDS;
        const uint32_t* pB = pA + SW_A;
#pragma unroll
        for (int ks = 0; ks < 4; ks++) {
            const int kb = ks * 8;
            uint32_t af[2][4];
#pragma unroll
            for (int mt = 0; mt < 2; mt++) {
                const int r0 = wm0 + mt * 16 + qrow;
                af[mt][0] = pA[r0 * APAD + kb + qcol];
                af[mt][1] = pA[(r0 + 8) * APAD + kb + qcol];
                af[mt][2] = pA[r0 * APAD + kb + qcol + 4];
                af[mt][3] = pA[(r0 + 8) * APAD + kb + qcol + 4];
            }
#pragma unroll
            for (int nt = 0; nt < 8; nt++) {
                const int c0 = wn0 + nt * 8 + qrow;
                uint32_t bf[2];
                bf[0] = pB[(kb + qcol) * BPAD + c0];
                bf[1] = pB[(kb + qcol + 4) * BPAD + c0];
                mma16n8k8(acc[0][nt], af[0], bf);
                mma16n8k8(acc[1][nt], af[1], bf);
            }
        }

        // ---- store next chunk into the other stage ----
        if (i + 1 < KC) {
            uint32_t* wA = smw + (1 - cur) * STG_WORDS;
            uint32_t* wB = wA + SW_A;
#pragma unroll
            for (int t = 0; t < 4; t++) {
                const int idx = t * 256 + tid;
                const int r = idx >> 3, c = (idx & 7) * 4;
                sts128(smem_u32(&wA[r * APAD + c]),
                       f2tf32(aR[t].x), f2tf32(aR[t].y),
                       f2tf32(aR[t].z), f2tf32(aR[t].w));
                const int k = idx >> 5, c2 = (idx & 31) * 4;
                sts128(smem_u32(&wB[k * BPAD + c2]),
                       f2tf32(bR[t].x), f2tf32(bR[t].y),
                       f2tf32(bR[t].z), f2tf32(bR[t].w));
            }
        }
        __syncthreads();
    }

    // ---- epilogue ----
#pragma unroll
    for (int mt = 0; mt < 2; mt++) {
        const int r0 = bm + wm0 + mt * 16 + qrow;
#pragma unroll
        for (int nt = 0; nt < 8; nt++) {
            const int c0 = bn + wn0 + nt * 8 + qcol * 2;
            const float2 bv = *(const float2*)&bias[c0];
#pragma unroll
            for (int half = 0; half < 2; half++) {
                const int row = r0 + half * 8;
                float2 v;
                v.x = acc[mt][nt][half * 2 + 0] + bv.x;
                v.y = acc[mt][nt][half * 2 + 1] + bv.y;
                if (EPI == 1) {
                    v.x = fmaxf(v.x, 0.f);
                    v.y = fmaxf(v.y, 0.f);
                }
                if (EPI == 2) {
                    const int b = row >> 11, s = row & 2047;
                    const int h = c0 >> 7, d = c0 & 127;
                    const size_t dst =
                        (((size_t)(b * NHEAD + h) * SEQ + s) * HDK) + d;
                    *(float2*)&C[dst] = v;
                } else {
                    *(float2*)&C[(size_t)row * N + c0] = v;
                }
            }
        }
    }
}

// ---------------- Flash attention (fp32, unchanged) ----------------
__global__ __launch_bounds__(256) void attn_kernel(
    const float* __restrict__ Q, const float* __restrict__ K,
    const float* __restrict__ V, float* __restrict__ Out)
{
    extern __shared__ float sm[];
    float* sQ  = sm;
    float* sK  = sm + 64 * 129;
    float* sV  = sm + 2 * 64 * 129;
    float* sS  = sm + 3 * 64 * 129;
    float* sMr = sS + 64 * 65;
    float* sLr = sMr + 64;
    float* sAl = sLr + 64;

    const int tid = threadIdx.x;
    const int bh = blockIdx.y;
    const int q0 = blockIdx.x * 64;

    const float* Qh = Q + (size_t)bh * SEQ * HDK;
    const float* Kh = K + (size_t)bh * SEQ * HDK;
    const float* Vh = V + (size_t)bh * SEQ * HDK;

    for (int idx = tid * 4; idx < 64 * 128; idx += 256 * 4) {
        const int r = idx >> 7, c = idx & 127;
        float4 v = *(const float4*)&Qh[(size_t)(q0 + r) * HDK + c];
        sQ[r * 129 + c + 0] = v.x;
        sQ[r * 129 + c + 1] = v.y;
        sQ[r * 129 + c + 2] = v.z;
        sQ[r * 129 + c + 3] = v.w;
    }
    if (tid < 64) { sMr[tid] = -INFINITY; sLr[tid] = 0.f; }

    const int i1 = (tid >> 4) * 4;
    const int j1 = (tid & 15) * 4;
    const int d3 = (tid & 15) * 8;

    float o[4][8];
#pragma unroll
    for (int i = 0; i < 4; i++)
#pragma unroll
        for (int d = 0; d < 8; d++) o[i][d] = 0.f;

    const float scale = 0.08838834764831845f;

    for (int kv0 = 0; kv0 < SEQ; kv0 += 64) {
        __syncthreads();
        for (int idx = tid * 4; idx < 64 * 128; idx += 256 * 4) {
            const int r = idx >> 7, c = idx & 127;
            float4 kv = *(const float4*)&Kh[(size_t)(kv0 + r) * HDK + c];
            sK[r * 129 + c + 0] = kv.x;
            sK[r * 129 + c + 1] = kv.y;
            sK[r * 129 + c + 2] = kv.z;
            sK[r * 129 + c + 3] = kv.w;
            float4 vv = *(const float4*)&Vh[(size_t)(kv0 + r) * HDK + c];
            sV[r * 129 + c + 0] = vv.x;
            sV[r * 129 + c + 1] = vv.y;
            sV[r * 129 + c + 2] = vv.z;
            sV[r * 129 + c + 3] = vv.w;
        }
        __syncthreads();

        float sa[4][4];
#pragma unroll
        for (int i = 0; i < 4; i++)
#pragma unroll
            for (int j = 0; j < 4; j++) sa[i][j] = 0.f;
#pragma unroll 8
        for (int k = 0; k < 128; k++) {
            float ra[4], rb[4];
#pragma unroll
            for (int ii = 0; ii < 4; ii++) ra[ii] = sQ[(i1 + ii) * 129 + k];
#pragma unroll
            for (int jj = 0; jj < 4; jj++) rb[jj] = sK[(j1 + jj) * 129 + k];
#pragma unroll
            for (int ii = 0; ii < 4; ii++)
#pragma unroll
                for (int jj = 0; jj < 4; jj++)
                    sa[ii][jj] = fmaf(ra[ii], rb[jj], sa[ii][jj]);
        }
#pragma unroll
        for (int ii = 0; ii < 4; ii++)
#pragma unroll
            for (int jj = 0; jj < 4; jj++)
                sS[(i1 + ii) * 65 + j1 + jj] = sa[ii][jj] * scale;
        __syncthreads();

        {
            const int row = tid >> 2, l4 = tid & 3;
            float* Sr = sS + row * 65 + l4 * 16;
            float tmax = -INFINITY;
#pragma unroll
            for (int j = 0; j < 16; j++) tmax = fmaxf(tmax, Sr[j]);
            tmax = fmaxf(tmax, __shfl_xor_sync(0xffffffffu, tmax, 1));
            tmax = fmaxf(tmax, __shfl_xor_sync(0xffffffffu, tmax, 2));
            const float mold = sMr[row];
            const float mnew = fmaxf(mold, tmax);
            float psum = 0.f;
#pragma unroll
            for (int j = 0; j < 16; j++) {
                const float p = __expf(Sr[j] - mnew);
                Sr[j] = p;
                psum += p;
            }
            psum += __shfl_xor_sync(0xffffffffu, psum, 1);
            psum += __shfl_xor_sync(0xffffffffu, psum, 2);
            if (l4 == 0) {
                const float alpha = __expf(mold - mnew);
                sAl[row] = alpha;
                sLr[row] = alpha * sLr[row] + psum;
                sMr[row] = mnew;
            }
        }
        __syncthreads();

        float al[4];
#pragma unroll
        for (int ii = 0; ii < 4; ii++) al[ii] = sAl[i1 + ii];
#pragma unroll
        for (int ii = 0; ii < 4; ii++)
#pragma unroll
            for (int dd = 0; dd < 8; dd++) o[ii][dd] *= al[ii];
#pragma unroll 4
        for (int kk = 0; kk < 64; kk++) {
            float rp[4], rv[8];
#pragma unroll
            for (int ii = 0; ii < 4; ii++) rp[ii] = sS[(i1 + ii) * 65 + kk];
#pragma unroll
            for (int dd = 0; dd < 8; dd++) rv[dd] = sV[kk * 129 + d3 + dd];
#pragma unroll
            for (int ii = 0; ii < 4; ii++)
#pragma unroll
                for (int dd = 0; dd < 8; dd++)
                    o[ii][dd] = fmaf(rp[ii], rv[dd], o[ii][dd]);
        }
    }

    const int b = bh >> 3, h = bh & 7;
#pragma unroll
    for (int ii = 0; ii < 4; ii++) {
        const int qrow = q0 + i1 + ii;
        const float linv = 1.f / sLr[i1 + ii];
        float* dst = Out + (size_t)(b * SEQ + qrow) * DMODEL + h * HDK + d3;
        float4 v0, v1;
        v0.x = o[ii][0] * linv; v0.y = o[ii][1] * linv;
        v0.z = o[ii][2] * linv; v0.w = o[ii][3] * linv;
        v1.x = o[ii][4] * linv; v1.y = o[ii][5] * linv;
        v1.z = o[ii][6] * linv; v1.w = o[ii][7] * linv;
        *(float4*)dst = v0;
        *(float4*)(dst + 4) = v1;
    }
}

// ---------------- residual add + LayerNorm ----------------
__global__ __launch_bounds__(256) void add_ln_kernel(
    const float* __restrict__ A, const float* __restrict__ B,
    const float* __restrict__ g, const float* __restrict__ beta,
    float* __restrict__ out)
{
    __shared__ float red[8];
    const int row = blockIdx.x, tid = threadIdx.x;
    const float* pa = A + (size_t)row * DMODEL;
    const float* pb = B + (size_t)row * DMODEL;

    float v[4];
    float s = 0.f;
#pragma unroll
    for (int i = 0; i < 4; i++) {
        const int c = tid + i * 256;
        v[i] = pa[c] + pb[c];
        s += v[i];
    }
#pragma unroll
    for (int off = 16; off; off >>= 1) s += __shfl_xor_sync(0xffffffffu, s, off);
    if ((tid & 31) == 0) red[tid >> 5] = s;
    __syncthreads();
    float tot = 0.f;
#pragma unroll
    for (int w = 0; w < 8; w++) tot += red[w];
    const float mu = tot * (1.f / 1024.f);

    float vs = 0.f;
#pragma unroll
    for (int i = 0; i < 4; i++) {
        const float d = v[i] - mu;
        vs += d * d;
    }
#pragma unroll
    for (int off = 16; off; off >>= 1) vs += __shfl_xor_sync(0xffffffffu, vs, off);
    __syncthreads();
    if ((tid & 31) == 0) red[tid >> 5] = vs;
    __syncthreads();
    float vtot = 0.f;
#pragma unroll
    for (int w = 0; w < 8; w++) vtot += red[w];
    const float rs = rsqrtf(vtot * (1.f / 1024.f) + 1e-6f);

    float* po = out + (size_t)row * DMODEL;
#pragma unroll
    for (int i = 0; i < 4; i++) {
        const int c = tid + i * 256;
        po[c] = (v[i] - mu) * rs * g[c] + beta[c];
    }
}

// ---------------- launch ----------------
extern "C" void kernel_launch(void* const* d_in, const int* in_sizes, int n_in,
                              void* d_out, int out_size)
{
    const float* x     = (const float*)d_in[0];
    const float* Wq    = (const float*)d_in[1];
    const float* bq    = (const float*)d_in[2];
    const float* Wk    = (const float*)d_in[3];
    const float* bk    = (const float*)d_in[4];
    const float* Wv    = (const float*)d_in[5];
    const float* bv    = (const float*)d_in[6];
    const float* ln1_g = (const float*)d_in[7];
    const float* ln1_b = (const float*)d_in[8];
    const float* W1    = (const float*)d_in[9];
    const float* b1    = (const float*)d_in[10];
    const float* W2    = (const float*)d_in[11];
    const float* b2    = (const float*)d_in[12];
    const float* ln2_g = (const float*)d_in[13];
    const float* ln2_b = (const float*)d_in[14];
    float* out = (float*)d_out;

    float *Qp, *Kp, *Vp, *Attp, *X1p, *H1p, *H2p;
    cudaGetSymbolAddress((void**)&Qp, gQ);
    cudaGetSymbolAddress((void**)&Kp, gK);
    cudaGetSymbolAddress((void**)&Vp, gV);
    cudaGetSymbolAddress((void**)&Attp, gAtt);
    cudaGetSymbolAddress((void**)&X1p, gX1);
    cudaGetSymbolAddress((void**)&H1p, gH1);
    cudaGetSymbolAddress((void**)&H2p, gH2);

    const dim3 blk(256);
    const int asmem = (3 * 64 * 129 + 64 * 65 + 3 * 64) * sizeof(float);
    static bool attr_done = false;
    if (!attr_done) {
        cudaFuncSetAttribute(tc_gemm<0>, cudaFuncAttributeMaxDynamicSharedMemorySize, GEMM_SMEM);
        cudaFuncSetAttribute(tc_gemm<1>, cudaFuncAttributeMaxDynamicSharedMemorySize, GEMM_SMEM);
        cudaFuncSetAttribute(tc_gemm<2>, cudaFuncAttributeMaxDynamicSharedMemorySize, GEMM_SMEM);
        cudaFuncSetAttribute(attn_kernel, cudaFuncAttributeMaxDynamicSharedMemorySize, asmem);
        attr_done = true;
    }

    // QKV projections (tf32 mma.sync), scattered into [B,H,S,dk]
    tc_gemm<2><<<dim3(8, 64), blk, GEMM_SMEM>>>(x, Wq, bq, Qp, NTOK, DMODEL, DMODEL);
    tc_gemm<2><<<dim3(8, 64), blk, GEMM_SMEM>>>(x, Wk, bk, Kp, NTOK, DMODEL, DMODEL);
    tc_gemm<2><<<dim3(8, 64), blk, GEMM_SMEM>>>(x, Wv, bv, Vp, NTOK, DMODEL, DMODEL);

    // flash attention
    attn_kernel<<<dim3(SEQ / 64, BATCH * NHEAD), blk, asmem>>>(Qp, Kp, Vp, Attp);

    // x1 = LN(att + x)
    add_ln_kernel<<<NTOK, blk>>>(Attp, x, ln1_g, ln1_b, X1p);

    // FFN (tf32 mma.sync)
    tc_gemm<1><<<dim3(32, 64), blk, GEMM_SMEM>>>(X1p, W1, b1, H1p, NTOK, DFF, DMODEL);
    tc_gemm<0><<<dim3(8, 64), blk, GEMM_SMEM>>>(H1p, W2, b2, H2p, NTOK, DMODEL, DFF);

    // out = LN(h2 + x1)
    add_ln_kernel<<<NTOK, blk>>>(H2p, X1p, ln2_g, ln2_b, out);
}

// round 13
// speedup vs baseline: 3.1916x; 1.8986x over previous
#include <cuda_runtime.h>
#include <math.h>
#include <stdint.h>

#define NTOK   8192      // B*S
#define DMODEL 1024
#define NHEAD  8
#define HDK    128
#define DFF    4096
#define SEQ    2048
#define BATCH  4

// ---------------- scratch (no allocations allowed) ----------------
__device__ float gQ[NTOK * DMODEL];     // [B,H,S,dk]
__device__ float gK[NTOK * DMODEL];
__device__ float gV[NTOK * DMODEL];
__device__ float gAtt[NTOK * DMODEL];   // [B,S,D]
__device__ float gX1[NTOK * DMODEL];
__device__ float gH1[(size_t)NTOK * DFF];
__device__ float gH2[NTOK * DMODEL];

// ============== helpers ==============
__device__ __forceinline__ uint32_t smem_u32(const void* p) {
    uint32_t a;
    asm("{ .reg .u64 t; cvta.to.shared.u64 t, %1; cvt.u32.u64 %0, t; }"
        : "=r"(a) : "l"(p));
    return a;
}
__device__ __forceinline__ uint32_t f2tf32(float x) {
    uint32_t u;
    asm("cvt.rna.tf32.f32 %0, %1;" : "=r"(u) : "f"(x));
    return u;
}
__device__ __forceinline__ void sts128(uint32_t addr, uint32_t a, uint32_t b,
                                       uint32_t c, uint32_t d) {
    asm volatile("st.shared.v4.b32 [%0], {%1,%2,%3,%4};"
                 :: "r"(addr), "r"(a), "r"(b), "r"(c), "r"(d) : "memory");
}
__device__ __forceinline__ void sts64(uint32_t addr, uint32_t a, uint32_t b) {
    asm volatile("st.shared.v2.b32 [%0], {%1,%2};"
                 :: "r"(addr), "r"(a), "r"(b) : "memory");
}
// m16n8k8 tf32 MMA (portable tensor-core path)
__device__ __forceinline__ void mma16n8k8(float* c, const uint32_t* a,
                                          const uint32_t* b) {
    asm volatile(
        "mma.sync.aligned.m16n8k8.row.col.f32.tf32.tf32.f32 "
        "{%0,%1,%2,%3}, {%4,%5,%6,%7}, {%8,%9}, {%0,%1,%2,%3};"
        : "+f"(c[0]), "+f"(c[1]), "+f"(c[2]), "+f"(c[3])
        : "r"(a[0]), "r"(a[1]), "r"(a[2]), "r"(a[3]), "r"(b[0]), "r"(b[1]));
}

// ============== tf32 tensor-core GEMM (unchanged from R8) ==============
#define BK 32
#define APAD 36
#define BPAD 136
#define SW_A (128 * APAD)
#define SW_B (BK * BPAD)
#define STG_WORDS (SW_A + SW_B)
#define GEMM_SMEM (2 * STG_WORDS * 4)

template <int EPI>
__global__ __launch_bounds__(256) void tc_gemm(
    const float* __restrict__ A, const float* __restrict__ B,
    const float* __restrict__ bias, float* __restrict__ C,
    int M, int N, int K)
{
    extern __shared__ uint32_t smw[];

    const int tid = threadIdx.x;
    const int wid = tid >> 5, lane = tid & 31;
    const int qrow = lane >> 2, qcol = lane & 3;
    const int wm0 = (wid & 3) * 32;
    const int wn0 = (wid >> 2) * 64;

    const int bm = blockIdx.y * 128;
    const int bn = blockIdx.x * 128;
    const int KC = K >> 5;

    float acc[2][8][4];
#pragma unroll
    for (int mt = 0; mt < 2; mt++)
#pragma unroll
        for (int nt = 0; nt < 8; nt++)
#pragma unroll
            for (int q = 0; q < 4; q++) acc[mt][nt][q] = 0.f;

    {
#pragma unroll
        for (int t = 0; t < 4; t++) {
            const int idx = t * 256 + tid;
            const int r = idx >> 3, c = (idx & 7) * 4;
            float4 v = *(const float4*)(A + (size_t)(bm + r) * K + c);
            sts128(smem_u32(&smw[r * APAD + c]),
                   f2tf32(v.x), f2tf32(v.y), f2tf32(v.z), f2tf32(v.w));
            const int k = idx >> 5, c2 = (idx & 31) * 4;
            float4 w = *(const float4*)(B + (size_t)k * N + bn + c2);
            sts128(smem_u32(&smw[SW_A + k * BPAD + c2]),
                   f2tf32(w.x), f2tf32(w.y), f2tf32(w.z), f2tf32(w.w));
        }
    }
    __syncthreads();

    for (int i = 0; i < KC; i++) {
        const int cur = i & 1;
        float4 aR[4], bR[4];
        if (i + 1 < KC) {
            const int k1 = (i + 1) << 5;
#pragma unroll
            for (int t = 0; t < 4; t++) {
                const int idx = t * 256 + tid;
                const int r = idx >> 3, c = (idx & 7) * 4;
                aR[t] = *(const float4*)(A + (size_t)(bm + r) * K + k1 + c);
                const int k = idx >> 5, c2 = (idx & 31) * 4;
                bR[t] = *(const float4*)(B + (size_t)(k1 + k) * N + bn + c2);
            }
        }

        const uint32_t* pA = smw + cur * STG_WORDS;
        const uint32_t* pB = pA + SW_A;
#pragma unroll
        for (int ks = 0; ks < 4; ks++) {
            const int kb = ks * 8;
            uint32_t af[2][4];
#pragma unroll
            for (int mt = 0; mt < 2; mt++) {
                const int r0 = wm0 + mt * 16 + qrow;
                af[mt][0] = pA[r0 * APAD + kb + qcol];
                af[mt][1] = pA[(r0 + 8) * APAD + kb + qcol];
                af[mt][2] = pA[r0 * APAD + kb + qcol + 4];
                af[mt][3] = pA[(r0 + 8) * APAD + kb + qcol + 4];
            }
#pragma unroll
            for (int nt = 0; nt < 8; nt++) {
                const int c0 = wn0 + nt * 8 + qrow;
                uint32_t bf[2];
                bf[0] = pB[(kb + qcol) * BPAD + c0];
                bf[1] = pB[(kb + qcol + 4) * BPAD + c0];
                mma16n8k8(acc[0][nt], af[0], bf);
                mma16n8k8(acc[1][nt], af[1], bf);
            }
        }

        if (i + 1 < KC) {
            uint32_t* wA = smw + (1 - cur) * STG_WORDS;
            uint32_t* wB = wA + SW_A;
#pragma unroll
            for (int t = 0; t < 4; t++) {
                const int idx = t * 256 + tid;
                const int r = idx >> 3, c = (idx & 7) * 4;
                sts128(smem_u32(&wA[r * APAD + c]),
                       f2tf32(aR[t].x), f2tf32(aR[t].y),
                       f2tf32(aR[t].z), f2tf32(aR[t].w));
                const int k = idx >> 5, c2 = (idx & 31) * 4;
                sts128(smem_u32(&wB[k * BPAD + c2]),
                       f2tf32(bR[t].x), f2tf32(bR[t].y),
                       f2tf32(bR[t].z), f2tf32(bR[t].w));
            }
        }
        __syncthreads();
    }

#pragma unroll
    for (int mt = 0; mt < 2; mt++) {
        const int r0 = bm + wm0 + mt * 16 + qrow;
#pragma unroll
        for (int nt = 0; nt < 8; nt++) {
            const int c0 = bn + wn0 + nt * 8 + qcol * 2;
            const float2 bv = *(const float2*)&bias[c0];
#pragma unroll
            for (int half = 0; half < 2; half++) {
                const int row = r0 + half * 8;
                float2 v;
                v.x = acc[mt][nt][half * 2 + 0] + bv.x;
                v.y = acc[mt][nt][half * 2 + 1] + bv.y;
                if (EPI == 1) {
                    v.x = fmaxf(v.x, 0.f);
                    v.y = fmaxf(v.y, 0.f);
                }
                if (EPI == 2) {
                    const int b = row >> 11, s = row & 2047;
                    const int h = c0 >> 7, d = c0 & 127;
                    const size_t dst =
                        (((size_t)(b * NHEAD + h) * SEQ + s) * HDK) + d;
                    *(float2*)&C[dst] = v;
                } else {
                    *(float2*)&C[(size_t)row * N + c0] = v;
                }
            }
        }
    }
}

// ============== Flash attention on mma.sync tf32 ==============
// Q tile 128, KV tile 64, dk=128. 8 warps x 16 query rows.
#define QT 128
#define KT 64
#define QPAD 132
#define KPAD 132
#define VPAD 136
#define PPAD 68
#define ATTN_WORDS (QT * QPAD + KT * KPAD + KT * VPAD + QT * PPAD)
#define ATTN_SMEM (ATTN_WORDS * 4)   // 171008 B

__global__ __launch_bounds__(256) void attn_mma(
    const float* __restrict__ Q, const float* __restrict__ K,
    const float* __restrict__ V, float* __restrict__ Out)
{
    extern __shared__ uint32_t sw[];
    uint32_t* sQ = sw;
    uint32_t* sK = sQ + QT * QPAD;
    uint32_t* sV = sK + KT * KPAD;
    uint32_t* sP = sV + KT * VPAD;

    const int tid = threadIdx.x, wid = tid >> 5, lane = tid & 31;
    const int qrow = lane >> 2, qcol = lane & 3;
    const int bh = blockIdx.y;
    const int q0 = blockIdx.x * QT;
    const int r0 = wid * 16;

    const float* Qh = Q + (size_t)bh * SEQ * HDK;
    const float* Kh = K + (size_t)bh * SEQ * HDK;
    const float* Vh = V + (size_t)bh * SEQ * HDK;

    const float scale = 0.08838834764831845f;   // 1/sqrt(128)

    // ---- load Q tile (scale folded in, tf32) ----
#pragma unroll
    for (int t = 0; t < 16; t++) {
        const int idx = t * 256 + tid;
        const int r = idx >> 5, c4 = (idx & 31) * 4;
        float4 v = *(const float4*)&Qh[(size_t)(q0 + r) * HDK + c4];
        sts128(smem_u32(&sQ[r * QPAD + c4]),
               f2tf32(v.x * scale), f2tf32(v.y * scale),
               f2tf32(v.z * scale), f2tf32(v.w * scale));
    }

    float m_a = -INFINITY, m_b = -INFINITY, l_a = 0.f, l_b = 0.f;
    float acc_o[16][4];
#pragma unroll
    for (int nt = 0; nt < 16; nt++)
#pragma unroll
        for (int q = 0; q < 4; q++) acc_o[nt][q] = 0.f;

    for (int kv0 = 0; kv0 < SEQ; kv0 += KT) {
        __syncthreads();   // prior PV reads of sK/sV done (and Q stores on iter 0)
        // ---- load K,V tiles (tf32) ----
#pragma unroll
        for (int t = 0; t < 8; t++) {
            const int idx = t * 256 + tid;
            const int r = idx >> 5, c4 = (idx & 31) * 4;
            float4 kv = *(const float4*)&Kh[(size_t)(kv0 + r) * HDK + c4];
            sts128(smem_u32(&sK[r * KPAD + c4]),
                   f2tf32(kv.x), f2tf32(kv.y), f2tf32(kv.z), f2tf32(kv.w));
            float4 vv = *(const float4*)&Vh[(size_t)(kv0 + r) * HDK + c4];
            sts128(smem_u32(&sV[r * VPAD + c4]),
                   f2tf32(vv.x), f2tf32(vv.y), f2tf32(vv.z), f2tf32(vv.w));
        }
        __syncthreads();

        // ---- S = Q @ K^T (scaled) ----
        float acc_s[8][4];
#pragma unroll
        for (int nt = 0; nt < 8; nt++)
#pragma unroll
            for (int q = 0; q < 4; q++) acc_s[nt][q] = 0.f;

#pragma unroll
        for (int ks = 0; ks < 16; ks++) {
            const int kb = ks * 8;
            uint32_t af[4];
            af[0] = sQ[(r0 + qrow) * QPAD + kb + qcol];
            af[1] = sQ[(r0 + qrow + 8) * QPAD + kb + qcol];
            af[2] = sQ[(r0 + qrow) * QPAD + kb + qcol + 4];
            af[3] = sQ[(r0 + qrow + 8) * QPAD + kb + qcol + 4];
#pragma unroll
            for (int nt = 0; nt < 8; nt++) {
                uint32_t bf[2];
                bf[0] = sK[(nt * 8 + qrow) * KPAD + kb + qcol];
                bf[1] = sK[(nt * 8 + qrow) * KPAD + kb + qcol + 4];
                mma16n8k8(acc_s[nt], af, bf);
            }
        }

        // ---- online softmax on S fragments ----
        float mx_a = -INFINITY, mx_b = -INFINITY;
#pragma unroll
        for (int nt = 0; nt < 8; nt++) {
            mx_a = fmaxf(mx_a, fmaxf(acc_s[nt][0], acc_s[nt][1]));
            mx_b = fmaxf(mx_b, fmaxf(acc_s[nt][2], acc_s[nt][3]));
        }
        mx_a = fmaxf(mx_a, __shfl_xor_sync(0xffffffffu, mx_a, 1));
        mx_a = fmaxf(mx_a, __shfl_xor_sync(0xffffffffu, mx_a, 2));
        mx_b = fmaxf(mx_b, __shfl_xor_sync(0xffffffffu, mx_b, 1));
        mx_b = fmaxf(mx_b, __shfl_xor_sync(0xffffffffu, mx_b, 2));

        const float mn_a = fmaxf(m_a, mx_a);
        const float mn_b = fmaxf(m_b, mx_b);
        const float al_a = __expf(m_a - mn_a);
        const float al_b = __expf(m_b - mn_b);
        m_a = mn_a; m_b = mn_b;

        float ps_a = 0.f, ps_b = 0.f;
#pragma unroll
        for (int nt = 0; nt < 8; nt++) {
            acc_s[nt][0] = __expf(acc_s[nt][0] - mn_a);
            acc_s[nt][1] = __expf(acc_s[nt][1] - mn_a);
            acc_s[nt][2] = __expf(acc_s[nt][2] - mn_b);
            acc_s[nt][3] = __expf(acc_s[nt][3] - mn_b);
            ps_a += acc_s[nt][0] + acc_s[nt][1];
            ps_b += acc_s[nt][2] + acc_s[nt][3];
        }
        ps_a += __shfl_xor_sync(0xffffffffu, ps_a, 1);
        ps_a += __shfl_xor_sync(0xffffffffu, ps_a, 2);
        ps_b += __shfl_xor_sync(0xffffffffu, ps_b, 1);
        ps_b += __shfl_xor_sync(0xffffffffu, ps_b, 2);
        l_a = l_a * al_a + ps_a;
        l_b = l_b * al_b + ps_b;

        // rescale O
#pragma unroll
        for (int nt = 0; nt < 16; nt++) {
            acc_o[nt][0] *= al_a;
            acc_o[nt][1] *= al_a;
            acc_o[nt][2] *= al_b;
            acc_o[nt][3] *= al_b;
        }

        // ---- write P (warp-private rows) as tf32 ----
#pragma unroll
        for (int nt = 0; nt < 8; nt++) {
            const int col = nt * 8 + qcol * 2;
            sts64(smem_u32(&sP[(r0 + qrow) * PPAD + col]),
                  f2tf32(acc_s[nt][0]), f2tf32(acc_s[nt][1]));
            sts64(smem_u32(&sP[(r0 + qrow + 8) * PPAD + col]),
                  f2tf32(acc_s[nt][2]), f2tf32(acc_s[nt][3]));
        }
        __syncwarp();

        // ---- O += P @ V ----
#pragma unroll
        for (int ks = 0; ks < 8; ks++) {
            const int kb = ks * 8;
            uint32_t af[4];
            af[0] = sP[(r0 + qrow) * PPAD + kb + qcol];
            af[1] = sP[(r0 + qrow + 8) * PPAD + kb + qcol];
            af[2] = sP[(r0 + qrow) * PPAD + kb + qcol + 4];
            af[3] = sP[(r0 + qrow + 8) * PPAD + kb + qcol + 4];
#pragma unroll
            for (int nt = 0; nt < 16; nt++) {
                uint32_t bf[2];
                bf[0] = sV[(kb + qcol) * VPAD + nt * 8 + qrow];
                bf[1] = sV[(kb + qcol + 4) * VPAD + nt * 8 + qrow];
                mma16n8k8(acc_o[nt], af, bf);
            }
        }
    }

    // ---- epilogue: divide by l, write [B,S,D] ----
    const float li_a = 1.f / l_a, li_b = 1.f / l_b;
    const int b = bh >> 3, h = bh & 7;
    const int row_a = q0 + r0 + qrow;
#pragma unroll
    for (int nt = 0; nt < 16; nt++) {
        const int col = h * HDK + nt * 8 + qcol * 2;
        float2 va, vb;
        va.x = acc_o[nt][0] * li_a; va.y = acc_o[nt][1] * li_a;
        vb.x = acc_o[nt][2] * li_b; vb.y = acc_o[nt][3] * li_b;
        *(float2*)&Out[(size_t)(b * SEQ + row_a) * DMODEL + col] = va;
        *(float2*)&Out[(size_t)(b * SEQ + row_a + 8) * DMODEL + col] = vb;
    }
}

// ---------------- residual add + LayerNorm ----------------
__global__ __launch_bounds__(256) void add_ln_kernel(
    const float* __restrict__ A, const float* __restrict__ B,
    const float* __restrict__ g, const float* __restrict__ beta,
    float* __restrict__ out)
{
    __shared__ float red[8];
    const int row = blockIdx.x, tid = threadIdx.x;
    const float* pa = A + (size_t)row * DMODEL;
    const float* pb = B + (size_t)row * DMODEL;

    float v[4];
    float s = 0.f;
#pragma unroll
    for (int i = 0; i < 4; i++) {
        const int c = tid + i * 256;
        v[i] = pa[c] + pb[c];
        s += v[i];
    }
#pragma unroll
    for (int off = 16; off; off >>= 1) s += __shfl_xor_sync(0xffffffffu, s, off);
    if ((tid & 31) == 0) red[tid >> 5] = s;
    __syncthreads();
    float tot = 0.f;
#pragma unroll
    for (int w = 0; w < 8; w++) tot += red[w];
    const float mu = tot * (1.f / 1024.f);

    float vs = 0.f;
#pragma unroll
    for (int i = 0; i < 4; i++) {
        const float d = v[i] - mu;
        vs += d * d;
    }
#pragma unroll
    for (int off = 16; off; off >>= 1) vs += __shfl_xor_sync(0xffffffffu, vs, off);
    __syncthreads();
    if ((tid & 31) == 0) red[tid >> 5] = vs;
    __syncthreads();
    float vtot = 0.f;
#pragma unroll
    for (int w = 0; w < 8; w++) vtot += red[w];
    const float rs = rsqrtf(vtot * (1.f / 1024.f) + 1e-6f);

    float* po = out + (size_t)row * DMODEL;
#pragma unroll
    for (int i = 0; i < 4; i++) {
        const int c = tid + i * 256;
        po[c] = (v[i] - mu) * rs * g[c] + beta[c];
    }
}

// ---------------- launch ----------------
extern "C" void kernel_launch(void* const* d_in, const int* in_sizes, int n_in,
                              void* d_out, int out_size)
{
    const float* x     = (const float*)d_in[0];
    const float* Wq    = (const float*)d_in[1];
    const float* bq    = (const float*)d_in[2];
    const float* Wk    = (const float*)d_in[3];
    const float* bk    = (const float*)d_in[4];
    const float* Wv    = (const float*)d_in[5];
    const float* bv    = (const float*)d_in[6];
    const float* ln1_g = (const float*)d_in[7];
    const float* ln1_b = (const float*)d_in[8];
    const float* W1    = (const float*)d_in[9];
    const float* b1    = (const float*)d_in[10];
    const float* W2    = (const float*)d_in[11];
    const float* b2    = (const float*)d_in[12];
    const float* ln2_g = (const float*)d_in[13];
    const float* ln2_b = (const float*)d_in[14];
    float* out = (float*)d_out;

    float *Qp, *Kp, *Vp, *Attp, *X1p, *H1p, *H2p;
    cudaGetSymbolAddress((void**)&Qp, gQ);
    cudaGetSymbolAddress((void**)&Kp, gK);
    cudaGetSymbolAddress((void**)&Vp, gV);
    cudaGetSymbolAddress((void**)&Attp, gAtt);
    cudaGetSymbolAddress((void**)&X1p, gX1);
    cudaGetSymbolAddress((void**)&H1p, gH1);
    cudaGetSymbolAddress((void**)&H2p, gH2);

    const dim3 blk(256);
    static bool attr_done = false;
    if (!attr_done) {
        cudaFuncSetAttribute(tc_gemm<0>, cudaFuncAttributeMaxDynamicSharedMemorySize, GEMM_SMEM);
        cudaFuncSetAttribute(tc_gemm<1>, cudaFuncAttributeMaxDynamicSharedMemorySize, GEMM_SMEM);
        cudaFuncSetAttribute(tc_gemm<2>, cudaFuncAttributeMaxDynamicSharedMemorySize, GEMM_SMEM);
        cudaFuncSetAttribute(attn_mma, cudaFuncAttributeMaxDynamicSharedMemorySize, ATTN_SMEM);
        attr_done = true;
    }

    // QKV projections (tf32 mma.sync), scattered into [B,H,S,dk]
    tc_gemm<2><<<dim3(8, 64), blk, GEMM_SMEM>>>(x, Wq, bq, Qp, NTOK, DMODEL, DMODEL);
    tc_gemm<2><<<dim3(8, 64), blk, GEMM_SMEM>>>(x, Wk, bk, Kp, NTOK, DMODEL, DMODEL);
    tc_gemm<2><<<dim3(8, 64), blk, GEMM_SMEM>>>(x, Wv, bv, Vp, NTOK, DMODEL, DMODEL);

    // flash attention (tf32 mma.sync)
    attn_mma<<<dim3(SEQ / QT, BATCH * NHEAD), blk, ATTN_SMEM>>>(Qp, Kp, Vp, Attp);

    // x1 = LN(att + x)
    add_ln_kernel<<<NTOK, blk>>>(Attp, x, ln1_g, ln1_b, X1p);

    // FFN (tf32 mma.sync)
    tc_gemm<1><<<dim3(32, 64), blk, GEMM_SMEM>>>(X1p, W1, b1, H1p, NTOK, DFF, DMODEL);
    tc_gemm<0><<<dim3(8, 64), blk, GEMM_SMEM>>>(H1p, W2, b2, H2p, NTOK, DMODEL, DFF);

    // out = LN(h2 + x1)
    add_ln_kernel<<<NTOK, blk>>>(H2p, X1p, ln2_g, ln2_b, out);
}

// round 16
// speedup vs baseline: 3.1938x; 1.0007x over previous
#include <cuda_runtime.h>
#include <math.h>
#include <stdint.h>

#define NTOK   8192      // B*S
#define DMODEL 1024
#define NHEAD  8
#define HDK    128
#define DFF    4096
#define SEQ    2048
#define BATCH  4

// ---------------- scratch (no allocations allowed) ----------------
__device__ float gQ[NTOK * DMODEL];     // [B,H,S,dk]
__device__ float gK[NTOK * DMODEL];
__device__ float gV[NTOK * DMODEL];
__device__ float gAtt[NTOK * DMODEL];   // [B,S,D]
__device__ float gX1[NTOK * DMODEL];
__device__ float gH1[(size_t)NTOK * DFF];
__device__ float gH2[NTOK * DMODEL];

// ============== helpers ==============
__device__ __forceinline__ uint32_t smem_u32(const void* p) {
    uint32_t a;
    asm("{ .reg .u64 t; cvta.to.shared.u64 t, %1; cvt.u32.u64 %0, t; }"
        : "=r"(a) : "l"(p));
    return a;
}
__device__ __forceinline__ uint32_t f2tf32(float x) {
    uint32_t u;
    asm("cvt.rna.tf32.f32 %0, %1;" : "=r"(u) : "f"(x));
    return u;
}
__device__ __forceinline__ void sts128(uint32_t addr, uint32_t a, uint32_t b,
                                       uint32_t c, uint32_t d) {
    asm volatile("st.shared.v4.b32 [%0], {%1,%2,%3,%4};"
                 :: "r"(addr), "r"(a), "r"(b), "r"(c), "r"(d) : "memory");
}
__device__ __forceinline__ void sts64(uint32_t addr, uint32_t a, uint32_t b) {
    asm volatile("st.shared.v2.b32 [%0], {%1,%2};"
                 :: "r"(addr), "r"(a), "r"(b) : "memory");
}
// m16n8k8 tf32 MMA (portable tensor-core path)
__device__ __forceinline__ void mma16n8k8(float* c, const uint32_t* a,
                                          const uint32_t* b) {
    asm volatile(
        "mma.sync.aligned.m16n8k8.row.col.f32.tf32.tf32.f32 "
        "{%0,%1,%2,%3}, {%4,%5,%6,%7}, {%8,%9}, {%0,%1,%2,%3};"
        : "+f"(c[0]), "+f"(c[1]), "+f"(c[2]), "+f"(c[3])
        : "r"(a[0]), "r"(a[1]), "r"(a[2]), "r"(a[3]), "r"(b[0]), "r"(b[1]));
}

// ============== tf32 tensor-core GEMM (unchanged from R8) ==============
#define BK 32
#define APAD 36
#define BPAD 136
#define SW_A (128 * APAD)
#define SW_B (BK * BPAD)
#define STG_WORDS (SW_A + SW_B)
#define GEMM_SMEM (2 * STG_WORDS * 4)

template <int EPI>
__global__ __launch_bounds__(256) void tc_gemm(
    const float* __restrict__ A, const float* __restrict__ B,
    const float* __restrict__ bias, float* __restrict__ C,
    int M, int N, int K)
{
    extern __shared__ uint32_t smw[];

    const int tid = threadIdx.x;
    const int wid = tid >> 5, lane = tid & 31;
    const int qrow = lane >> 2, qcol = lane & 3;
    const int wm0 = (wid & 3) * 32;
    const int wn0 = (wid >> 2) * 64;

    const int bm = blockIdx.y * 128;
    const int bn = blockIdx.x * 128;
    const int KC = K >> 5;

    float acc[2][8][4];
#pragma unroll
    for (int mt = 0; mt < 2; mt++)
#pragma unroll
        for (int nt = 0; nt < 8; nt++)
#pragma unroll
            for (int q = 0; q < 4; q++) acc[mt][nt][q] = 0.f;

    {
#pragma unroll
        for (int t = 0; t < 4; t++) {
            const int idx = t * 256 + tid;
            const int r = idx >> 3, c = (idx & 7) * 4;
            float4 v = *(const float4*)(A + (size_t)(bm + r) * K + c);
            sts128(smem_u32(&smw[r * APAD + c]),
                   f2tf32(v.x), f2tf32(v.y), f2tf32(v.z), f2tf32(v.w));
            const int k = idx >> 5, c2 = (idx & 31) * 4;
            float4 w = *(const float4*)(B + (size_t)k * N + bn + c2);
            sts128(smem_u32(&smw[SW_A + k * BPAD + c2]),
                   f2tf32(w.x), f2tf32(w.y), f2tf32(w.z), f2tf32(w.w));
        }
    }
    __syncthreads();

    for (int i = 0; i < KC; i++) {
        const int cur = i & 1;
        float4 aR[4], bR[4];
        if (i + 1 < KC) {
            const int k1 = (i + 1) << 5;
#pragma unroll
            for (int t = 0; t < 4; t++) {
                const int idx = t * 256 + tid;
                const int r = idx >> 3, c = (idx & 7) * 4;
                aR[t] = *(const float4*)(A + (size_t)(bm + r) * K + k1 + c);
                const int k = idx >> 5, c2 = (idx & 31) * 4;
                bR[t] = *(const float4*)(B + (size_t)(k1 + k) * N + bn + c2);
            }
        }

        const uint32_t* pA = smw + cur * STG_WORDS;
        const uint32_t* pB = pA + SW_A;
#pragma unroll
        for (int ks = 0; ks < 4; ks++) {
            const int kb = ks * 8;
            uint32_t af[2][4];
#pragma unroll
            for (int mt = 0; mt < 2; mt++) {
                const int r0 = wm0 + mt * 16 + qrow;
                af[mt][0] = pA[r0 * APAD + kb + qcol];
                af[mt][1] = pA[(r0 + 8) * APAD + kb + qcol];
                af[mt][2] = pA[r0 * APAD + kb + qcol + 4];
                af[mt][3] = pA[(r0 + 8) * APAD + kb + qcol + 4];
            }
#pragma unroll
            for (int nt = 0; nt < 8; nt++) {
                const int c0 = wn0 + nt * 8 + qrow;
                uint32_t bf[2];
                bf[0] = pB[(kb + qcol) * BPAD + c0];
                bf[1] = pB[(kb + qcol + 4) * BPAD + c0];
                mma16n8k8(acc[0][nt], af[0], bf);
                mma16n8k8(acc[1][nt], af[1], bf);
            }
        }

        if (i + 1 < KC) {
            uint32_t* wA = smw + (1 - cur) * STG_WORDS;
            uint32_t* wB = wA + SW_A;
#pragma unroll
            for (int t = 0; t < 4; t++) {
                const int idx = t * 256 + tid;
                const int r = idx >> 3, c = (idx & 7) * 4;
                sts128(smem_u32(&wA[r * APAD + c]),
                       f2tf32(aR[t].x), f2tf32(aR[t].y),
                       f2tf32(aR[t].z), f2tf32(aR[t].w));
                const int k = idx >> 5, c2 = (idx & 31) * 4;
                sts128(smem_u32(&wB[k * BPAD + c2]),
                       f2tf32(bR[t].x), f2tf32(bR[t].y),
                       f2tf32(bR[t].z), f2tf32(bR[t].w));
            }
        }
        __syncthreads();
    }

#pragma unroll
    for (int mt = 0; mt < 2; mt++) {
        const int r0 = bm + wm0 + mt * 16 + qrow;
#pragma unroll
        for (int nt = 0; nt < 8; nt++) {
            const int c0 = bn + wn0 + nt * 8 + qcol * 2;
            const float2 bv = *(const float2*)&bias[c0];
#pragma unroll
            for (int half = 0; half < 2; half++) {
                const int row = r0 + half * 8;
                float2 v;
                v.x = acc[mt][nt][half * 2 + 0] + bv.x;
                v.y = acc[mt][nt][half * 2 + 1] + bv.y;
                if (EPI == 1) {
                    v.x = fmaxf(v.x, 0.f);
                    v.y = fmaxf(v.y, 0.f);
                }
                if (EPI == 2) {
                    const int b = row >> 11, s = row & 2047;
                    const int h = c0 >> 7, d = c0 & 127;
                    const size_t dst =
                        (((size_t)(b * NHEAD + h) * SEQ + s) * HDK) + d;
                    *(float2*)&C[dst] = v;
                } else {
                    *(float2*)&C[(size_t)row * N + c0] = v;
                }
            }
        }
    }
}

// ============== Flash attention on mma.sync tf32 ==============
// Q tile 128, KV tile 64, dk=128. 8 warps x 16 query rows.
#define QT 128
#define KT 64
#define QPAD 132
#define KPAD 132
#define VPAD 136
#define PPAD 68
#define ATTN_WORDS (QT * QPAD + KT * KPAD + KT * VPAD + QT * PPAD)
#define ATTN_SMEM (ATTN_WORDS * 4)   // 171008 B

__global__ __launch_bounds__(256) void attn_mma(
    const float* __restrict__ Q, const float* __restrict__ K,
    const float* __restrict__ V, float* __restrict__ Out)
{
    extern __shared__ uint32_t sw[];
    uint32_t* sQ = sw;
    uint32_t* sK = sQ + QT * QPAD;
    uint32_t* sV = sK + KT * KPAD;
    uint32_t* sP = sV + KT * VPAD;

    const int tid = threadIdx.x, wid = tid >> 5, lane = tid & 31;
    const int qrow = lane >> 2, qcol = lane & 3;
    const int bh = blockIdx.y;
    const int q0 = blockIdx.x * QT;
    const int r0 = wid * 16;

    const float* Qh = Q + (size_t)bh * SEQ * HDK;
    const float* Kh = K + (size_t)bh * SEQ * HDK;
    const float* Vh = V + (size_t)bh * SEQ * HDK;

    const float scale = 0.08838834764831845f;   // 1/sqrt(128)

    // ---- load Q tile (scale folded in, tf32) ----
#pragma unroll
    for (int t = 0; t < 16; t++) {
        const int idx = t * 256 + tid;
        const int r = idx >> 5, c4 = (idx & 31) * 4;
        float4 v = *(const float4*)&Qh[(size_t)(q0 + r) * HDK + c4];
        sts128(smem_u32(&sQ[r * QPAD + c4]),
               f2tf32(v.x * scale), f2tf32(v.y * scale),
               f2tf32(v.z * scale), f2tf32(v.w * scale));
    }

    float m_a = -INFINITY, m_b = -INFINITY, l_a = 0.f, l_b = 0.f;
    float acc_o[16][4];
#pragma unroll
    for (int nt = 0; nt < 16; nt++)
#pragma unroll
        for (int q = 0; q < 4; q++) acc_o[nt][q] = 0.f;

    for (int kv0 = 0; kv0 < SEQ; kv0 += KT) {
        __syncthreads();   // prior PV reads of sK/sV done (and Q stores on iter 0)
        // ---- load K,V tiles (tf32) ----
#pragma unroll
        for (int t = 0; t < 8; t++) {
            const int idx = t * 256 + tid;
            const int r = idx >> 5, c4 = (idx & 31) * 4;
            float4 kv = *(const float4*)&Kh[(size_t)(kv0 + r) * HDK + c4];
            sts128(smem_u32(&sK[r * KPAD + c4]),
                   f2tf32(kv.x), f2tf32(kv.y), f2tf32(kv.z), f2tf32(kv.w));
            float4 vv = *(const float4*)&Vh[(size_t)(kv0 + r) * HDK + c4];
            sts128(smem_u32(&sV[r * VPAD + c4]),
                   f2tf32(vv.x), f2tf32(vv.y), f2tf32(vv.z), f2tf32(vv.w));
        }
        __syncthreads();

        // ---- S = Q @ K^T (scaled) ----
        float acc_s[8][4];
#pragma unroll
        for (int nt = 0; nt < 8; nt++)
#pragma unroll
            for (int q = 0; q < 4; q++) acc_s[nt][q] = 0.f;

#pragma unroll
        for (int ks = 0; ks < 16; ks++) {
            const int kb = ks * 8;
            uint32_t af[4];
            af[0] = sQ[(r0 + qrow) * QPAD + kb + qcol];
            af[1] = sQ[(r0 + qrow + 8) * QPAD + kb + qcol];
            af[2] = sQ[(r0 + qrow) * QPAD + kb + qcol + 4];
            af[3] = sQ[(r0 + qrow + 8) * QPAD + kb + qcol + 4];
#pragma unroll
            for (int nt = 0; nt < 8; nt++) {
                uint32_t bf[2];
                bf[0] = sK[(nt * 8 + qrow) * KPAD + kb + qcol];
                bf[1] = sK[(nt * 8 + qrow) * KPAD + kb + qcol + 4];
                mma16n8k8(acc_s[nt], af, bf);
            }
        }

        // ---- online softmax on S fragments ----
        float mx_a = -INFINITY, mx_b = -INFINITY;
#pragma unroll
        for (int nt = 0; nt < 8; nt++) {
            mx_a = fmaxf(mx_a, fmaxf(acc_s[nt][0], acc_s[nt][1]));
            mx_b = fmaxf(mx_b, fmaxf(acc_s[nt][2], acc_s[nt][3]));
        }
        mx_a = fmaxf(mx_a, __shfl_xor_sync(0xffffffffu, mx_a, 1));
        mx_a = fmaxf(mx_a, __shfl_xor_sync(0xffffffffu, mx_a, 2));
        mx_b = fmaxf(mx_b, __shfl_xor_sync(0xffffffffu, mx_b, 1));
        mx_b = fmaxf(mx_b, __shfl_xor_sync(0xffffffffu, mx_b, 2));

        const float mn_a = fmaxf(m_a, mx_a);
        const float mn_b = fmaxf(m_b, mx_b);
        const float al_a = __expf(m_a - mn_a);
        const float al_b = __expf(m_b - mn_b);
        m_a = mn_a; m_b = mn_b;

        float ps_a = 0.f, ps_b = 0.f;
#pragma unroll
        for (int nt = 0; nt < 8; nt++) {
            acc_s[nt][0] = __expf(acc_s[nt][0] - mn_a);
            acc_s[nt][1] = __expf(acc_s[nt][1] - mn_a);
            acc_s[nt][2] = __expf(acc_s[nt][2] - mn_b);
            acc_s[nt][3] = __expf(acc_s[nt][3] - mn_b);
            ps_a += acc_s[nt][0] + acc_s[nt][1];
            ps_b += acc_s[nt][2] + acc_s[nt][3];
        }
        ps_a += __shfl_xor_sync(0xffffffffu, ps_a, 1);
        ps_a += __shfl_xor_sync(0xffffffffu, ps_a, 2);
        ps_b += __shfl_xor_sync(0xffffffffu, ps_b, 1);
        ps_b += __shfl_xor_sync(0xffffffffu, ps_b, 2);
        l_a = l_a * al_a + ps_a;
        l_b = l_b * al_b + ps_b;

        // rescale O
#pragma unroll
        for (int nt = 0; nt < 16; nt++) {
            acc_o[nt][0] *= al_a;
            acc_o[nt][1] *= al_a;
            acc_o[nt][2] *= al_b;
            acc_o[nt][3] *= al_b;
        }

        // ---- write P (warp-private rows) as tf32 ----
#pragma unroll
        for (int nt = 0; nt < 8; nt++) {
            const int col = nt * 8 + qcol * 2;
            sts64(smem_u32(&sP[(r0 + qrow) * PPAD + col]),
                  f2tf32(acc_s[nt][0]), f2tf32(acc_s[nt][1]));
            sts64(smem_u32(&sP[(r0 + qrow + 8) * PPAD + col]),
                  f2tf32(acc_s[nt][2]), f2tf32(acc_s[nt][3]));
        }
        __syncwarp();

        // ---- O += P @ V ----
#pragma unroll
        for (int ks = 0; ks < 8; ks++) {
            const int kb = ks * 8;
            uint32_t af[4];
            af[0] = sP[(r0 + qrow) * PPAD + kb + qcol];
            af[1] = sP[(r0 + qrow + 8) * PPAD + kb + qcol];
            af[2] = sP[(r0 + qrow) * PPAD + kb + qcol + 4];
            af[3] = sP[(r0 + qrow + 8) * PPAD + kb + qcol + 4];
#pragma unroll
            for (int nt = 0; nt < 16; nt++) {
                uint32_t bf[2];
                bf[0] = sV[(kb + qcol) * VPAD + nt * 8 + qrow];
                bf[1] = sV[(kb + qcol + 4) * VPAD + nt * 8 + qrow];
                mma16n8k8(acc_o[nt], af, bf);
            }
        }
    }

    // ---- epilogue: divide by l, write [B,S,D] ----
    const float li_a = 1.f / l_a, li_b = 1.f / l_b;
    const int b = bh >> 3, h = bh & 7;
    const int row_a = q0 + r0 + qrow;
#pragma unroll
    for (int nt = 0; nt < 16; nt++) {
        const int col = h * HDK + nt * 8 + qcol * 2;
        float2 va, vb;
        va.x = acc_o[nt][0] * li_a; va.y = acc_o[nt][1] * li_a;
        vb.x = acc_o[nt][2] * li_b; vb.y = acc_o[nt][3] * li_b;
        *(float2*)&Out[(size_t)(b * SEQ + row_a) * DMODEL + col] = va;
        *(float2*)&Out[(size_t)(b * SEQ + row_a + 8) * DMODEL + col] = vb;
    }
}

// ---------------- residual add + LayerNorm ----------------
__global__ __launch_bounds__(256) void add_ln_kernel(
    const float* __restrict__ A, const float* __restrict__ B,
    const float* __restrict__ g, const float* __restrict__ beta,
    float* __restrict__ out)
{
    __shared__ float red[8];
    const int row = blockIdx.x, tid = threadIdx.x;
    const float* pa = A + (size_t)row * DMODEL;
    const float* pb = B + (size_t)row * DMODEL;

    float v[4];
    float s = 0.f;
#pragma unroll
    for (int i = 0; i < 4; i++) {
        const int c = tid + i * 256;
        v[i] = pa[c] + pb[c];
        s += v[i];
    }
#pragma unroll
    for (int off = 16; off; off >>= 1) s += __shfl_xor_sync(0xffffffffu, s, off);
    if ((tid & 31) == 0) red[tid >> 5] = s;
    __syncthreads();
    float tot = 0.f;
#pragma unroll
    for (int w = 0; w < 8; w++) tot += red[w];
    const float mu = tot * (1.f / 1024.f);

    float vs = 0.f;
#pragma unroll
    for (int i = 0; i < 4; i++) {
        const float d = v[i] - mu;
        vs += d * d;
    }
#pragma unroll
    for (int off = 16; off; off >>= 1) vs += __shfl_xor_sync(0xffffffffu, vs, off);
    __syncthreads();
    if ((tid & 31) == 0) red[tid >> 5] = vs;
    __syncthreads();
    float vtot = 0.f;
#pragma unroll
    for (int w = 0; w < 8; w++) vtot += red[w];
    const float rs = rsqrtf(vtot * (1.f / 1024.f) + 1e-6f);

    float* po = out + (size_t)row * DMODEL;
#pragma unroll
    for (int i = 0; i < 4; i++) {
        const int c = tid + i * 256;
        po[c] = (v[i] - mu) * rs * g[c] + beta[c];
    }
}

// ---------------- launch ----------------
extern "C" void kernel_launch(void* const* d_in, const int* in_sizes, int n_in,
                              void* d_out, int out_size)
{
    const float* x     = (const float*)d_in[0];
    const float* Wq    = (const float*)d_in[1];
    const float* bq    = (const float*)d_in[2];
    const float* Wk    = (const float*)d_in[3];
    const float* bk    = (const float*)d_in[4];
    const float* Wv    = (const float*)d_in[5];
    const float* bv    = (const float*)d_in[6];
    const float* ln1_g = (const float*)d_in[7];
    const float* ln1_b = (const float*)d_in[8];
    const float* W1    = (const float*)d_in[9];
    const float* b1    = (const float*)d_in[10];
    const float* W2    = (const float*)d_in[11];
    const float* b2    = (const float*)d_in[12];
    const float* ln2_g = (const float*)d_in[13];
    const float* ln2_b = (const float*)d_in[14];
    float* out = (float*)d_out;

    float *Qp, *Kp, *Vp, *Attp, *X1p, *H1p, *H2p;
    cudaGetSymbolAddress((void**)&Qp, gQ);
    cudaGetSymbolAddress((void**)&Kp, gK);
    cudaGetSymbolAddress((void**)&Vp, gV);
    cudaGetSymbolAddress((void**)&Attp, gAtt);
    cudaGetSymbolAddress((void**)&X1p, gX1);
    cudaGetSymbolAddress((void**)&H1p, gH1);
    cudaGetSymbolAddress((void**)&H2p, gH2);

    const dim3 blk(256);
    static bool attr_done = false;
    if (!attr_done) {
        cudaFuncSetAttribute(tc_gemm<0>, cudaFuncAttributeMaxDynamicSharedMemorySize, GEMM_SMEM);
        cudaFuncSetAttribute(tc_gemm<1>, cudaFuncAttributeMaxDynamicSharedMemorySize, GEMM_SMEM);
        cudaFuncSetAttribute(tc_gemm<2>, cudaFuncAttributeMaxDynamicSharedMemorySize, GEMM_SMEM);
        cudaFuncSetAttribute(attn_mma, cudaFuncAttributeMaxDynamicSharedMemorySize, ATTN_SMEM);
        attr_done = true;
    }

    // QKV projections (tf32 mma.sync), scattered into [B,H,S,dk]
    tc_gemm<2><<<dim3(8, 64), blk, GEMM_SMEM>>>(x, Wq, bq, Qp, NTOK, DMODEL, DMODEL);
    tc_gemm<2><<<dim3(8, 64), blk, GEMM_SMEM>>>(x, Wk, bk, Kp, NTOK, DMODEL, DMODEL);
    tc_gemm<2><<<dim3(8, 64), blk, GEMM_SMEM>>>(x, Wv, bv, Vp, NTOK, DMODEL, DMODEL);

    // flash attention (tf32 mma.sync)
    attn_mma<<<dim3(SEQ / QT, BATCH * NHEAD), blk, ATTN_SMEM>>>(Qp, Kp, Vp, Attp);

    // x1 = LN(att + x)
    add_ln_kernel<<<NTOK, blk>>>(Attp, x, ln1_g, ln1_b, X1p);

    // FFN (tf32 mma.sync)
    tc_gemm<1><<<dim3(32, 64), blk, GEMM_SMEM>>>(X1p, W1, b1, H1p, NTOK, DFF, DMODEL);
    tc_gemm<0><<<dim3(8, 64), blk, GEMM_SMEM>>>(H1p, W2, b2, H2p, NTOK, DMODEL, DFF);

    // out = LN(h2 + x1)
    add_ln_kernel<<<NTOK, blk>>>(H2p, X1p, ln2_g, ln2_b, out);
}